// round 7
// baseline (speedup 1.0000x reference)
#include <cuda_runtime.h>
#include <cuda_bf16.h>
#include <cstdint>

// ---------------- problem constants ----------------
#define CC   128
#define HH   96
#define WW   128
#define PP   (HH * WW)      // 12288 (M)
#define HRR  96
#define WRR  128
#define QQ   (HRR * WRR)    // 12288 (N)

// ---------------- tiling ----------------
#define BM    128           // CTA m-tile
#define BN    256           // CTA n-tile
#define NQT   (QQ / BN)     // 48 q-tiles
#define NS    4             // n-splits (grid.y)
#define TPC   (NQT / NS)    // 12 tiles per CTA
#define STAGES (3 * TPC)    // 3 B-variant stages per tile

#define A_IMG_BYTES   32768                  // one A variant image per mt (fragment-ready)
#define B_IMG_BYTES   65536                  // one B variant image per qt (fragment-ready)
#define SMEM_A_OFF    1024
#define SMEM_B0_OFF   (SMEM_A_OFF + 3 * A_IMG_BYTES)       // 99328
#define SMEM_B1_OFF   (SMEM_B0_OFF + B_IMG_BYTES)          // 164864
#define SMEM_TOTAL    (SMEM_B1_OFF + B_IMG_BYTES)          // 230400 <= 232448

// ---------------- device scratch (no allocs allowed) ----------------
// A: [mt 96][variant 3][s 8][mf 8][lane 32] uint4  (fragment-ready)
__device__ uint4 gA4[96 * 3 * 8 * 8 * 32];
// B: [qt 48][variant 3][s 8][wn 4][lane 32][r4 4] uint4 (fragment-ready)
__device__ uint4 gB4[48 * 3 * 8 * 4 * 32 * 4];
__device__ unsigned long long g_best[PP];

// ---------------- helpers ----------------
__device__ __forceinline__ uint32_t smem_u32(const void* p) {
    uint32_t a;
    asm("{ .reg .u64 t; cvta.to.shared.u64 t, %1; cvt.u32.u64 %0, t; }" : "=r"(a) : "l"(p));
    return a;
}
__device__ __forceinline__ unsigned int fkey(float f) {
    unsigned int b = __float_as_uint(f);
    return (b & 0x80000000u) ? ~b : (b | 0x80000000u);
}
__device__ __forceinline__ unsigned short bf16_bits(float x) {
    __nv_bfloat16 h = __float2bfloat16(x);
    return *reinterpret_cast<unsigned short*>(&h);
}
__device__ __forceinline__ float bf16_val(unsigned short b) {
    __nv_bfloat16 h = *reinterpret_cast<__nv_bfloat16*>(&b);
    return __bfloat162float(h);
}
// 3-term bf16 split: a = hi + mid + lo (+ ~2^-32 residual)
__device__ __forceinline__ void split3(float a, unsigned short& h, unsigned short& m,
                                       unsigned short& l) {
    h = bf16_bits(a);
    float r1 = a - bf16_val(h);
    m = bf16_bits(r1);
    float r2 = r1 - bf16_val(m);
    l = bf16_bits(r2);
}

// ---------------- mbarrier ----------------
#define MBAR_INIT(a, n) \
    asm volatile("mbarrier.init.shared.b64 [%0], %1;" :: "r"(a), "r"((uint32_t)(n)) : "memory")
#define MBAR_EXPECT_TX(a, n) \
    asm volatile("mbarrier.arrive.expect_tx.shared.b64 _, [%0], %1;" :: "r"(a), "r"((uint32_t)(n)) : "memory")

__device__ __forceinline__ void mbar_wait(uint32_t mbar, uint32_t phase) {
    asm volatile(
        "{\n\t.reg .pred P1;\n\t"
        "W_%=:\n\t"
        "mbarrier.try_wait.parity.acquire.cta.shared::cta.b64 P1, [%0], %1, 0x989680;\n\t"
        "@P1 bra.uni D_%=;\n\t"
        "bra.uni W_%=;\n\t"
        "D_%=:\n\t}"
        :: "r"(mbar), "r"(phase) : "memory");
}

// ---------------- legacy tensor-core mma (baseline PTX, works on sm_103) ----------------
__device__ __forceinline__ void mma16816(float* d, uint32_t a0, uint32_t a1, uint32_t a2,
                                         uint32_t a3, uint32_t b0, uint32_t b1) {
    asm volatile(
        "mma.sync.aligned.m16n8k16.row.col.f32.bf16.bf16.f32 "
        "{%0,%1,%2,%3}, {%4,%5,%6,%7}, {%8,%9}, {%0,%1,%2,%3};"
        : "+f"(d[0]), "+f"(d[1]), "+f"(d[2]), "+f"(d[3])
        : "r"(a0), "r"(a1), "r"(a2), "r"(a3), "r"(b0), "r"(b1));
}

// ---------------- precompute: fragment-ready bf16 splits ----------------
__global__ void splitA_kernel(const float* __restrict__ fl) {
    int idx = blockIdx.x * 256 + threadIdx.x;          // 96*8*8*32 = 196608
    int lane = idx & 31, mf = (idx >> 5) & 7, s = (idx >> 8) & 7, mt = idx >> 11;
    int g = lane >> 2, t = lane & 3;
    int M = mt * 128 + mf * 16 + g;
    int K = s * 16 + 2 * t;
    // reg order: (M,K)(M,K+1) | (M+8,K)(M+8,K+1) | (M,K+8)(M,K+9) | (M+8,K+8)(M+8,K+9)
    float v[8];
    v[0] = fl[(size_t)K * PP + M];       v[1] = fl[(size_t)(K + 1) * PP + M];
    v[2] = fl[(size_t)K * PP + M + 8];   v[3] = fl[(size_t)(K + 1) * PP + M + 8];
    v[4] = fl[(size_t)(K + 8) * PP + M]; v[5] = fl[(size_t)(K + 9) * PP + M];
    v[6] = fl[(size_t)(K + 8) * PP + M + 8]; v[7] = fl[(size_t)(K + 9) * PP + M + 8];
    unsigned short hh[8], mm[8], ll[8];
    #pragma unroll
    for (int k = 0; k < 8; ++k) split3(v[k], hh[k], mm[k], ll[k]);
    size_t base = ((size_t)(mt * 3) * 8 + s) * 8 + mf;   // variant stride = 8*8 in (s,mf) units
    #pragma unroll
    for (int va = 0; va < 3; ++va) {
        const unsigned short* p = (va == 0) ? hh : (va == 1) ? mm : ll;
        uint4 o;
        o.x = ((uint32_t)p[1] << 16) | p[0];
        o.y = ((uint32_t)p[3] << 16) | p[2];
        o.z = ((uint32_t)p[5] << 16) | p[4];
        o.w = ((uint32_t)p[7] << 16) | p[6];
        gA4[(base + (size_t)va * 64) * 32 + lane] = o;
    }
}

__global__ void splitB_kernel(const float* __restrict__ fr) {
    int idx = blockIdx.x * 256 + threadIdx.x;          // 48*8*4*32*4 = 196608
    int r4 = idx & 3, lane = (idx >> 2) & 31, wn = (idx >> 7) & 3;
    int s = (idx >> 9) & 7, qt = idx >> 12;
    int g = lane >> 2, t = lane & 3;
    int k0 = s * 16 + 2 * t;
    uint32_t regs[3][4];                                // [variant][j0b0,j0b1,j1b0,j1b1]
    #pragma unroll
    for (int h2 = 0; h2 < 2; ++h2) {
        int j = 2 * r4 + h2;
        int n = qt * 256 + wn * 64 + j * 8 + g;
        float v0 = fr[(size_t)k0 * QQ + n];
        float v1 = fr[(size_t)(k0 + 1) * QQ + n];
        float v8 = fr[(size_t)(k0 + 8) * QQ + n];
        float v9 = fr[(size_t)(k0 + 9) * QQ + n];
        unsigned short h0[3], h1[3], h8[3], h9[3];
        split3(v0, h0[0], h0[1], h0[2]);
        split3(v1, h1[0], h1[1], h1[2]);
        split3(v8, h8[0], h8[1], h8[2]);
        split3(v9, h9[0], h9[1], h9[2]);
        #pragma unroll
        for (int vv = 0; vv < 3; ++vv) {
            regs[vv][2 * h2]     = ((uint32_t)h1[vv] << 16) | h0[vv];   // b0: (k0,n)(k0+1,n)
            regs[vv][2 * h2 + 1] = ((uint32_t)h9[vv] << 16) | h8[vv];   // b1: (k0+8,n)(k0+9,n)
        }
    }
    #pragma unroll
    for (int vv = 0; vv < 3; ++vv) {
        size_t o = ((((size_t)(qt * 3 + vv) * 8 + s) * 4 + wn) * 32 + lane) * 4 + r4;
        gB4[o] = make_uint4(regs[vv][0], regs[vv][1], regs[vv][2], regs[vv][3]);
    }
}

__global__ void init_best_kernel() {
    int p = blockIdx.x * blockDim.x + threadIdx.x;
    if (p < PP) g_best[p] = 0ull;
}

// ---------------- main GEMM + fused argmax ----------------
__global__ void __launch_bounds__(256, 1)
corr_mma_kernel() {
    extern __shared__ char smem[];
    const uint32_t sb = smem_u32(smem);
    const int tid = threadIdx.x, lane = tid & 31, wid = tid >> 5;
    const int wm = wid >> 2, wn = wid & 3;           // 2 m-warps x 4 n-warps
    const int g = lane >> 2, t = lane & 3;
    const int mt = blockIdx.x, ns = blockIdx.y;
    const int tile0 = ns * TPC;

    if (tid == 0) { MBAR_INIT(sb + 0, 1); MBAR_INIT(sb + 8, 1); }

    // A images (3 variants, 96KB) -> resident SMEM, coalesced
    {
        const uint4* srcA = gA4 + (size_t)mt * 3 * 2048;
        uint4* dstA = reinterpret_cast<uint4*>(smem + SMEM_A_OFF);
        #pragma unroll
        for (int i = 0; i < 24; ++i) dstA[i * 256 + tid] = srcA[i * 256 + tid];
    }
    __syncthreads();

    // issue stage 0 copy
    if (tid == 0) {
        MBAR_EXPECT_TX(sb + 0, B_IMG_BYTES);
        const char* src = reinterpret_cast<const char*>(gB4) +
                          (size_t)(tile0 * 3 + 0) * B_IMG_BYTES;
        asm volatile(
            "cp.async.bulk.shared::cluster.global.mbarrier::complete_tx::bytes "
            "[%0], [%1], %2, [%3];"
            :: "r"(sb + SMEM_B0_OFF), "l"(src), "r"((uint32_t)B_IMG_BYTES),
               "r"(sb + 0) : "memory");
    }

    float acc[128];
    float bv[8];
    int bq[8];
    #pragma unroll
    for (int i = 0; i < 8; ++i) { bv[i] = -3.402823466e38f; bq[i] = 0; }

    uint32_t phase[2] = {0, 0};

    for (int st = 0; st < STAGES; ++st) {
        const int b = st & 1;
        const int tile = tile0 + st / 3;
        const int vb = st - (st / 3) * 3;

        // producer: issue next stage into the other buffer
        // (safe: previous consumers of that buffer passed last stage's __syncthreads)
        if (tid == 0 && st + 1 < STAGES) {
            int b2 = (st + 1) & 1;
            int tile2 = tile0 + (st + 1) / 3;
            int vb2 = (st + 1) - ((st + 1) / 3) * 3;
            MBAR_EXPECT_TX(sb + 8 * b2, B_IMG_BYTES);
            const char* src = reinterpret_cast<const char*>(gB4) +
                              (size_t)(tile2 * 3 + vb2) * B_IMG_BYTES;
            asm volatile(
                "cp.async.bulk.shared::cluster.global.mbarrier::complete_tx::bytes "
                "[%0], [%1], %2, [%3];"
                :: "r"(sb + (b2 ? SMEM_B1_OFF : SMEM_B0_OFF)), "l"(src),
                   "r"((uint32_t)B_IMG_BYTES), "r"(sb + 8 * b2) : "memory");
        }

        if (vb == 0) {
            #pragma unroll
            for (int i = 0; i < 128; ++i) acc[i] = 0.0f;
        }

        mbar_wait(sb + 8 * b, phase[b]); phase[b] ^= 1;
        const char* Bb = smem + (b ? SMEM_B1_OFF : SMEM_B0_OFF);

        const int nva = 3 - vb;        // vb0:{hi,mid,lo}x, vb1:{hi,mid}, vb2:{hi}
        for (int va = 0; va < nva; ++va) {
            const char* Av = smem + SMEM_A_OFF + va * A_IMG_BYTES;
            #pragma unroll
            for (int s = 0; s < 8; ++s) {
                uint4 af[4];
                #pragma unroll
                for (int i = 0; i < 4; ++i)
                    af[i] = *reinterpret_cast<const uint4*>(
                        Av + (((s * 8 + (4 * wm + i)) * 32 + lane) << 4));
                uint4 bfm[4];
                const uint4* bp = reinterpret_cast<const uint4*>(
                    Bb + (((s * 4 + wn) * 32 + lane) << 6));
                #pragma unroll
                for (int j = 0; j < 4; ++j) bfm[j] = bp[j];

                #pragma unroll
                for (int i = 0; i < 4; ++i) {
                    #pragma unroll
                    for (int r = 0; r < 4; ++r) {
                        mma16816(&acc[(i * 8 + 2 * r) * 4],
                                 af[i].x, af[i].y, af[i].z, af[i].w, bfm[r].x, bfm[r].y);
                        mma16816(&acc[(i * 8 + 2 * r + 1) * 4],
                                 af[i].x, af[i].y, af[i].z, af[i].w, bfm[r].z, bfm[r].w);
                    }
                }
            }
        }

        if (vb == 2) {
            // all 6 passes done for this tile: fold into running argmax (q ascending)
            const int q0 = tile * 256 + wn * 64;
            #pragma unroll
            for (int i = 0; i < 4; ++i)
                #pragma unroll
                for (int j = 0; j < 8; ++j) {
                    int qb = q0 + j * 8 + 2 * t;
                    #pragma unroll
                    for (int c = 0; c < 4; ++c) {
                        float v = acc[(i * 8 + j) * 4 + c];
                        int slot = i * 2 + (c >> 1);
                        int q = qb + (c & 1);
                        if (v > bv[slot]) { bv[slot] = v; bq[slot] = q; }
                    }
                }
        }
        __syncthreads();   // buffer-reuse protocol
    }

    // reduce across the 4 lanes sharing the same rows (t = 0..3)
    #pragma unroll
    for (int off = 1; off < 4; off <<= 1) {
        #pragma unroll
        for (int s2 = 0; s2 < 8; ++s2) {
            float ov = __shfl_xor_sync(0xFFFFFFFFu, bv[s2], off);
            int oq = __shfl_xor_sync(0xFFFFFFFFu, bq[s2], off);
            if (ov > bv[s2] || (ov == bv[s2] && oq < bq[s2])) { bv[s2] = ov; bq[s2] = oq; }
        }
    }
    if (t == 0) {
        #pragma unroll
        for (int s2 = 0; s2 < 8; ++s2) {
            int row = mt * 128 + (4 * wm + (s2 >> 1)) * 16 + g + (s2 & 1) * 8;
            unsigned long long pk = ((unsigned long long)fkey(bv[s2]) << 32) |
                                    (0xFFFFFFFFu - (unsigned)bq[s2]);
            atomicMax(&g_best[row], pk);
        }
    }
}

// ---------------- decode ----------------
__global__ void decode_kernel(float* __restrict__ out,
                              const int* __restrict__ sxp,
                              const int* __restrict__ syp) {
    int p = blockIdx.x * blockDim.x + threadIdx.x;
    if (p >= PP) return;
    int sx = sxp ? *sxp : 4;
    int sy = syp ? *syp : 4;

    unsigned long long pk = g_best[p];
    unsigned int key = (unsigned int)(pk >> 32);
    unsigned int idx = 0xFFFFFFFFu - (unsigned int)(pk & 0xFFFFFFFFu);
    float val = (key & 0x80000000u) ? __uint_as_float(key ^ 0x80000000u)
                                    : __uint_as_float(~key);
    int h = p / WW, w = p % WW;
    int i = (int)(idx / WRR), j = (int)(idx % WRR);

    out[2 * p + 0]  = (float)(w - j * sx);
    out[2 * p + 1]  = (float)(h - i * sy);
    out[2 * PP + p] = val;
}

// ---------------- launch ----------------
extern "C" void kernel_launch(void* const* d_in, const int* in_sizes, int n_in,
                              void* d_out, int out_size) {
    const float* fl = (const float*)d_in[0];
    const float* fr = (const float*)d_in[1];
    const int* sxp = (n_in > 2) ? (const int*)d_in[2] : nullptr;
    const int* syp = (n_in > 3) ? (const int*)d_in[3] : nullptr;
    float* out = (float*)d_out;
    (void)in_sizes; (void)out_size;

    cudaFuncSetAttribute(corr_mma_kernel,
                         cudaFuncAttributeMaxDynamicSharedMemorySize, SMEM_TOTAL);

    splitA_kernel<<<768, 256>>>(fl);
    splitB_kernel<<<768, 256>>>(fr);
    init_best_kernel<<<(PP + 255) / 256, 256>>>();
    corr_mma_kernel<<<dim3(PP / BM, NS), 256, SMEM_TOTAL>>>();
    decode_kernel<<<(PP + 255) / 256, 256>>>(out, sxp, syp);
}

// round 8
// speedup vs baseline: 2.2891x; 2.2891x over previous
#include <cuda_runtime.h>
#include <cuda_fp16.h>
#include <cstdint>

// ---------------- problem constants ----------------
#define CC   128
#define HH   96
#define WW   128
#define PP   (HH * WW)      // 12288 (M)
#define HRR  96
#define WRR  128
#define QQ   (HRR * WRR)    // 12288 (N)

// ---------------- tiling ----------------
#define BM    128           // CTA m-tile
#define BN    256           // CTA n-tile
#define NQT   (QQ / BN)     // 48 q-tiles
#define NS    4             // n-splits (grid.y)
#define TPC   (NQT / NS)    // 12 tiles per CTA
#define STAGES (2 * TPC)    // 2 B-variant stages per tile (hi, lo)

#define A_IMG_BYTES   32768                  // one A variant image per mt (fragment-ready)
#define B_IMG_BYTES   65536                  // one B variant image per qt (fragment-ready)
#define SMEM_A_OFF    1024
#define SMEM_B0_OFF   (SMEM_A_OFF + 2 * A_IMG_BYTES)       // 66560
#define SMEM_B1_OFF   (SMEM_B0_OFF + B_IMG_BYTES)          // 132096
#define SMEM_TOTAL    (SMEM_B1_OFF + B_IMG_BYTES)          // 197632

// ---------------- device scratch (no allocs allowed) ----------------
// A: [mt 96][variant 2][s 8][mf 8][lane 32] uint4  (fragment-ready fp16 pairs)
__device__ uint4 gA4[96 * 2 * 8 * 8 * 32];
// B: [qt 48][variant 2][s 8][wn 4][r4 4][lane 32] uint4 (fragment-ready, lane-contiguous)
__device__ uint4 gB4[48 * 2 * 8 * 4 * 4 * 32];
__device__ unsigned long long g_best[PP];

// ---------------- helpers ----------------
__device__ __forceinline__ uint32_t smem_u32(const void* p) {
    uint32_t a;
    asm("{ .reg .u64 t; cvta.to.shared.u64 t, %1; cvt.u32.u64 %0, t; }" : "=r"(a) : "l"(p));
    return a;
}
__device__ __forceinline__ unsigned int fkey(float f) {
    unsigned int b = __float_as_uint(f);
    return (b & 0x80000000u) ? ~b : (b | 0x80000000u);
}
__device__ __forceinline__ unsigned short h16(float x) {
    __half h = __float2half_rn(x);
    return *reinterpret_cast<unsigned short*>(&h);
}
__device__ __forceinline__ float h16v(unsigned short b) {
    __half h = *reinterpret_cast<__half*>(&b);
    return __half2float(h);
}
// 2-term fp16 split: a = hi + lo (+ ~2^-22 residual)
__device__ __forceinline__ void split2(float a, unsigned short& hi, unsigned short& lo) {
    hi = h16(a);
    lo = h16(a - h16v(hi));
}

// ---------------- mbarrier ----------------
#define MBAR_INIT(a, n) \
    asm volatile("mbarrier.init.shared.b64 [%0], %1;" :: "r"(a), "r"((uint32_t)(n)) : "memory")
#define MBAR_EXPECT_TX(a, n) \
    asm volatile("mbarrier.arrive.expect_tx.shared.b64 _, [%0], %1;" :: "r"(a), "r"((uint32_t)(n)) : "memory")

__device__ __forceinline__ void mbar_wait(uint32_t mbar, uint32_t phase) {
    asm volatile(
        "{\n\t.reg .pred P1;\n\t"
        "W_%=:\n\t"
        "mbarrier.try_wait.parity.acquire.cta.shared::cta.b64 P1, [%0], %1, 0x989680;\n\t"
        "@P1 bra.uni D_%=;\n\t"
        "bra.uni W_%=;\n\t"
        "D_%=:\n\t}"
        :: "r"(mbar), "r"(phase) : "memory");
}

// ---------------- legacy tensor-core mma (baseline PTX, sm_103-safe) ----------------
__device__ __forceinline__ void mma16816(float* d, uint32_t a0, uint32_t a1, uint32_t a2,
                                         uint32_t a3, uint32_t b0, uint32_t b1) {
    asm volatile(
        "mma.sync.aligned.m16n8k16.row.col.f32.f16.f16.f32 "
        "{%0,%1,%2,%3}, {%4,%5,%6,%7}, {%8,%9}, {%0,%1,%2,%3};"
        : "+f"(d[0]), "+f"(d[1]), "+f"(d[2]), "+f"(d[3])
        : "r"(a0), "r"(a1), "r"(a2), "r"(a3), "r"(b0), "r"(b1));
}

// ---------------- precompute: fragment-ready fp16 splits ----------------
__global__ void splitA_kernel(const float* __restrict__ fl) {
    int idx = blockIdx.x * 256 + threadIdx.x;          // 96*8*8*32 = 196608
    int lane = idx & 31, mf = (idx >> 5) & 7, s = (idx >> 8) & 7, mt = idx >> 11;
    int g = lane >> 2, t = lane & 3;
    int M = mt * 128 + mf * 16 + g;
    int K = s * 16 + 2 * t;
    // reg order: (M,K)(M,K+1) | (M+8,K)(M+8,K+1) | (M,K+8)(M,K+9) | (M+8,K+8)(M+8,K+9)
    float v[8];
    v[0] = fl[(size_t)K * PP + M];           v[1] = fl[(size_t)(K + 1) * PP + M];
    v[2] = fl[(size_t)K * PP + M + 8];       v[3] = fl[(size_t)(K + 1) * PP + M + 8];
    v[4] = fl[(size_t)(K + 8) * PP + M];     v[5] = fl[(size_t)(K + 9) * PP + M];
    v[6] = fl[(size_t)(K + 8) * PP + M + 8]; v[7] = fl[(size_t)(K + 9) * PP + M + 8];
    unsigned short hh[8], ll[8];
    #pragma unroll
    for (int k = 0; k < 8; ++k) split2(v[k], hh[k], ll[k]);
    size_t base = ((size_t)(mt * 2) * 8 + s) * 8 + mf;   // variant stride = 64 (s,mf) units
    #pragma unroll
    for (int va = 0; va < 2; ++va) {
        const unsigned short* p = (va == 0) ? hh : ll;
        uint4 o;
        o.x = ((uint32_t)p[1] << 16) | p[0];
        o.y = ((uint32_t)p[3] << 16) | p[2];
        o.z = ((uint32_t)p[5] << 16) | p[4];
        o.w = ((uint32_t)p[7] << 16) | p[6];
        gA4[(base + (size_t)va * 64) * 32 + lane] = o;
    }
}

__global__ void splitB_kernel(const float* __restrict__ fr) {
    int idx = blockIdx.x * 256 + threadIdx.x;          // 48*8*4*4*32 = 196608
    int lane = idx & 31, r4 = (idx >> 5) & 3, wn = (idx >> 7) & 3;
    int s = (idx >> 9) & 7, qt = idx >> 12;
    int g = lane >> 2, t = lane & 3;
    int k0 = s * 16 + 2 * t;
    uint32_t regs[2][4];                                // [variant][j0b0,j0b1,j1b0,j1b1]
    #pragma unroll
    for (int h2 = 0; h2 < 2; ++h2) {
        int j = 2 * r4 + h2;
        int n = qt * 256 + wn * 64 + j * 8 + g;
        float v0 = fr[(size_t)k0 * QQ + n];
        float v1 = fr[(size_t)(k0 + 1) * QQ + n];
        float v8 = fr[(size_t)(k0 + 8) * QQ + n];
        float v9 = fr[(size_t)(k0 + 9) * QQ + n];
        unsigned short h0[2], h1[2], h8[2], h9[2];
        split2(v0, h0[0], h0[1]);
        split2(v1, h1[0], h1[1]);
        split2(v8, h8[0], h8[1]);
        split2(v9, h9[0], h9[1]);
        #pragma unroll
        for (int vv = 0; vv < 2; ++vv) {
            regs[vv][2 * h2]     = ((uint32_t)h1[vv] << 16) | h0[vv];   // b0: (k0,n)(k0+1,n)
            regs[vv][2 * h2 + 1] = ((uint32_t)h9[vv] << 16) | h8[vv];   // b1: (k0+8..9,n)
        }
    }
    #pragma unroll
    for (int vv = 0; vv < 2; ++vv) {
        // lane-contiguous: [qt][vv][s][wn][r4][lane]
        size_t o = ((((size_t)(qt * 2 + vv) * 8 + s) * 4 + wn) * 4 + r4) * 32 + lane;
        gB4[o] = make_uint4(regs[vv][0], regs[vv][1], regs[vv][2], regs[vv][3]);
    }
}

__global__ void init_best_kernel() {
    int p = blockIdx.x * blockDim.x + threadIdx.x;
    if (p < PP) g_best[p] = 0ull;
}

// ---------------- main GEMM + fused argmax ----------------
__global__ void __launch_bounds__(256, 1)
corr_mma_kernel() {
    extern __shared__ char smem[];
    const uint32_t sb = smem_u32(smem);
    const int tid = threadIdx.x, lane = tid & 31, wid = tid >> 5;
    const int wm = wid >> 2, wn = wid & 3;           // 2 m-warps x 4 n-warps
    const int g = lane >> 2, t = lane & 3;
    const int mt = blockIdx.x, ns = blockIdx.y;
    const int tile0 = ns * TPC;

    if (tid == 0) { MBAR_INIT(sb + 0, 1); MBAR_INIT(sb + 8, 1); }

    // A images (2 variants, 64KB) -> resident SMEM, coalesced
    {
        const uint4* srcA = gA4 + (size_t)mt * 2 * 2048;
        uint4* dstA = reinterpret_cast<uint4*>(smem + SMEM_A_OFF);
        #pragma unroll
        for (int i = 0; i < 16; ++i) dstA[i * 256 + tid] = srcA[i * 256 + tid];
    }
    __syncthreads();

    // issue stage 0 copy
    if (tid == 0) {
        MBAR_EXPECT_TX(sb + 0, B_IMG_BYTES);
        const char* src = reinterpret_cast<const char*>(gB4) +
                          (size_t)(tile0 * 2 + 0) * B_IMG_BYTES;
        asm volatile(
            "cp.async.bulk.shared::cluster.global.mbarrier::complete_tx::bytes "
            "[%0], [%1], %2, [%3];"
            :: "r"(sb + SMEM_B0_OFF), "l"(src), "r"((uint32_t)B_IMG_BYTES),
               "r"(sb + 0) : "memory");
    }

    float acc[128];
    float bv[8];
    int bq[8];
    #pragma unroll
    for (int i = 0; i < 8; ++i) { bv[i] = -3.402823466e38f; bq[i] = 0; }

    uint32_t phase[2] = {0, 0};

    for (int st = 0; st < STAGES; ++st) {
        const int b = st & 1;
        const int tile = tile0 + (st >> 1);
        const int vb = st & 1;           // 0: B=hi (A passes hi,lo), 1: B=lo (A pass hi)

        // producer: issue next stage into the other buffer
        if (tid == 0 && st + 1 < STAGES) {
            int b2 = (st + 1) & 1;
            int tile2 = tile0 + ((st + 1) >> 1);
            int vb2 = (st + 1) & 1;
            MBAR_EXPECT_TX(sb + 8 * b2, B_IMG_BYTES);
            const char* src = reinterpret_cast<const char*>(gB4) +
                              (size_t)(tile2 * 2 + vb2) * B_IMG_BYTES;
            asm volatile(
                "cp.async.bulk.shared::cluster.global.mbarrier::complete_tx::bytes "
                "[%0], [%1], %2, [%3];"
                :: "r"(sb + (b2 ? SMEM_B1_OFF : SMEM_B0_OFF)), "l"(src),
                   "r"((uint32_t)B_IMG_BYTES), "r"(sb + 8 * b2) : "memory");
        }

        if (vb == 0) {
            #pragma unroll
            for (int i = 0; i < 128; ++i) acc[i] = 0.0f;
        }

        mbar_wait(sb + 8 * b, phase[b]); phase[b] ^= 1;
        const char* Bb = smem + (b ? SMEM_B1_OFF : SMEM_B0_OFF);

        const int nva = 2 - vb;
        #pragma unroll
        for (int s = 0; s < 8; ++s) {
            // B fragments once per k-step, conflict-free lane-contiguous LDS.128
            uint4 bfm[4];
            const uint4* bp = reinterpret_cast<const uint4*>(Bb) + ((s * 4 + wn) << 7);
            #pragma unroll
            for (int r = 0; r < 4; ++r) bfm[r] = bp[r * 32 + lane];

            for (int va = 0; va < nva; ++va) {
                const char* Av = smem + SMEM_A_OFF + va * A_IMG_BYTES;
                uint4 af[4];
                #pragma unroll
                for (int i = 0; i < 4; ++i)
                    af[i] = *reinterpret_cast<const uint4*>(
                        Av + (((s * 8 + (4 * wm + i)) * 32 + lane) << 4));

                #pragma unroll
                for (int i = 0; i < 4; ++i) {
                    #pragma unroll
                    for (int r = 0; r < 4; ++r) {
                        mma16816(&acc[(i * 8 + 2 * r) * 4],
                                 af[i].x, af[i].y, af[i].z, af[i].w, bfm[r].x, bfm[r].y);
                        mma16816(&acc[(i * 8 + 2 * r + 1) * 4],
                                 af[i].x, af[i].y, af[i].z, af[i].w, bfm[r].z, bfm[r].w);
                    }
                }
            }
        }

        if (vb == 1) {
            // all 3 passes done for this tile: fold into running argmax (q ascending)
            const int q0 = tile * 256 + wn * 64;
            #pragma unroll
            for (int i = 0; i < 4; ++i)
                #pragma unroll
                for (int j = 0; j < 8; ++j) {
                    int qb = q0 + j * 8 + 2 * t;
                    #pragma unroll
                    for (int c = 0; c < 4; ++c) {
                        float v = acc[(i * 8 + j) * 4 + c];
                        int slot = i * 2 + (c >> 1);
                        int q = qb + (c & 1);
                        if (v > bv[slot]) { bv[slot] = v; bq[slot] = q; }
                    }
                }
        }
        __syncthreads();   // buffer-reuse protocol
    }

    // reduce across the 4 lanes sharing the same rows (t = 0..3)
    #pragma unroll
    for (int off = 1; off < 4; off <<= 1) {
        #pragma unroll
        for (int s2 = 0; s2 < 8; ++s2) {
            float ov = __shfl_xor_sync(0xFFFFFFFFu, bv[s2], off);
            int oq = __shfl_xor_sync(0xFFFFFFFFu, bq[s2], off);
            if (ov > bv[s2] || (ov == bv[s2] && oq < bq[s2])) { bv[s2] = ov; bq[s2] = oq; }
        }
    }
    if (t == 0) {
        #pragma unroll
        for (int s2 = 0; s2 < 8; ++s2) {
            int row = mt * 128 + (4 * wm + (s2 >> 1)) * 16 + g + (s2 & 1) * 8;
            unsigned long long pk = ((unsigned long long)fkey(bv[s2]) << 32) |
                                    (0xFFFFFFFFu - (unsigned)bq[s2]);
            atomicMax(&g_best[row], pk);
        }
    }
}

// ---------------- decode ----------------
__global__ void decode_kernel(float* __restrict__ out,
                              const int* __restrict__ sxp,
                              const int* __restrict__ syp) {
    int p = blockIdx.x * blockDim.x + threadIdx.x;
    if (p >= PP) return;
    int sx = sxp ? *sxp : 4;
    int sy = syp ? *syp : 4;

    unsigned long long pk = g_best[p];
    unsigned int key = (unsigned int)(pk >> 32);
    unsigned int idx = 0xFFFFFFFFu - (unsigned int)(pk & 0xFFFFFFFFu);
    float val = (key & 0x80000000u) ? __uint_as_float(key ^ 0x80000000u)
                                    : __uint_as_float(~key);
    int h = p / WW, w = p % WW;
    int i = (int)(idx / WRR), j = (int)(idx % WRR);

    out[2 * p + 0]  = (float)(w - j * sx);
    out[2 * p + 1]  = (float)(h - i * sy);
    out[2 * PP + p] = val;
}

// ---------------- launch ----------------
extern "C" void kernel_launch(void* const* d_in, const int* in_sizes, int n_in,
                              void* d_out, int out_size) {
    const float* fl = (const float*)d_in[0];
    const float* fr = (const float*)d_in[1];
    const int* sxp = (n_in > 2) ? (const int*)d_in[2] : nullptr;
    const int* syp = (n_in > 3) ? (const int*)d_in[3] : nullptr;
    float* out = (float*)d_out;
    (void)in_sizes; (void)out_size;

    cudaFuncSetAttribute(corr_mma_kernel,
                         cudaFuncAttributeMaxDynamicSharedMemorySize, SMEM_TOTAL);

    splitA_kernel<<<768, 256>>>(fl);
    splitB_kernel<<<768, 256>>>(fr);
    init_best_kernel<<<(PP + 255) / 256, 256>>>();
    corr_mma_kernel<<<dim3(PP / BM, NS), 256, SMEM_TOTAL>>>();
    decode_kernel<<<(PP + 255) / 256, 256>>>(out, sxp, syp);
}

// round 9
// speedup vs baseline: 2.5526x; 1.1151x over previous
#include <cuda_runtime.h>
#include <cuda_fp16.h>
#include <cstdint>

// ---------------- problem constants ----------------
#define CC   128
#define HH   96
#define WW   128
#define PP   (HH * WW)      // 12288 (M)
#define HRR  96
#define WRR  128
#define QQ   (HRR * WRR)    // 12288 (N)

// ---------------- tiling ----------------
#define BM    128           // CTA m-tile
#define BN    256           // CTA n-tile
#define NQT   (QQ / BN)     // 48 q-tiles
#define NS    3             // n-splits (grid.y) -> 288 CTAs = 2 waves @ 94.7%
#define TPC   (NQT / NS)    // 16 tiles per CTA
#define STAGES (2 * TPC)    // 2 B-variant stages per tile (hi, lo)

#define A_IMG_BYTES   32768                  // one A variant image per mt (fragment-ready)
#define B_IMG_BYTES   65536                  // one B variant image per qt (fragment-ready)
#define SMEM_A_OFF    1024
#define SMEM_B0_OFF   (SMEM_A_OFF + 2 * A_IMG_BYTES)       // 66560
#define SMEM_B1_OFF   (SMEM_B0_OFF + B_IMG_BYTES)          // 132096
#define SMEM_TOTAL    (SMEM_B1_OFF + B_IMG_BYTES)          // 197632

// ---------------- device scratch (no allocs allowed) ----------------
// A: [mt 96][variant 2][s 8][mf 8][lane 32] uint4  (fragment-ready fp16 pairs)
__device__ uint4 gA4[96 * 2 * 8 * 8 * 32];
// B: [qt 48][variant 2][s 8][wn 4][r4 4][lane 32] uint4 (fragment-ready, lane-contiguous)
__device__ uint4 gB4[48 * 2 * 8 * 4 * 4 * 32];
__device__ unsigned long long g_best[PP];

// ---------------- helpers ----------------
__device__ __forceinline__ uint32_t smem_u32(const void* p) {
    uint32_t a;
    asm("{ .reg .u64 t; cvta.to.shared.u64 t, %1; cvt.u32.u64 %0, t; }" : "=r"(a) : "l"(p));
    return a;
}
__device__ __forceinline__ unsigned int fkey(float f) {
    unsigned int b = __float_as_uint(f);
    return (b & 0x80000000u) ? ~b : (b | 0x80000000u);
}
__device__ __forceinline__ unsigned short h16(float x) {
    __half h = __float2half_rn(x);
    return *reinterpret_cast<unsigned short*>(&h);
}
__device__ __forceinline__ float h16v(unsigned short b) {
    __half h = *reinterpret_cast<__half*>(&b);
    return __half2float(h);
}
// 2-term fp16 split: a = hi + lo (+ ~2^-22 residual)
__device__ __forceinline__ void split2(float a, unsigned short& hi, unsigned short& lo) {
    hi = h16(a);
    lo = h16(a - h16v(hi));
}

// ---------------- mbarrier ----------------
#define MBAR_INIT(a, n) \
    asm volatile("mbarrier.init.shared.b64 [%0], %1;" :: "r"(a), "r"((uint32_t)(n)) : "memory")
#define MBAR_EXPECT_TX(a, n) \
    asm volatile("mbarrier.arrive.expect_tx.shared.b64 _, [%0], %1;" :: "r"(a), "r"((uint32_t)(n)) : "memory")

__device__ __forceinline__ void mbar_wait(uint32_t mbar, uint32_t phase) {
    asm volatile(
        "{\n\t.reg .pred P1;\n\t"
        "W_%=:\n\t"
        "mbarrier.try_wait.parity.acquire.cta.shared::cta.b64 P1, [%0], %1, 0x989680;\n\t"
        "@P1 bra.uni D_%=;\n\t"
        "bra.uni W_%=;\n\t"
        "D_%=:\n\t}"
        :: "r"(mbar), "r"(phase) : "memory");
}

// ---------------- legacy tensor-core mma (baseline PTX, sm_103-safe) ----------------
__device__ __forceinline__ void mma16816(float* d, uint32_t a0, uint32_t a1, uint32_t a2,
                                         uint32_t a3, uint32_t b0, uint32_t b1) {
    asm volatile(
        "mma.sync.aligned.m16n8k16.row.col.f32.f16.f16.f32 "
        "{%0,%1,%2,%3}, {%4,%5,%6,%7}, {%8,%9}, {%0,%1,%2,%3};"
        : "+f"(d[0]), "+f"(d[1]), "+f"(d[2]), "+f"(d[3])
        : "r"(a0), "r"(a1), "r"(a2), "r"(a3), "r"(b0), "r"(b1));
}

// ---------------- precompute: fragment-ready fp16 splits ----------------
__global__ void splitA_kernel(const float* __restrict__ fl) {
    int idx = blockIdx.x * 256 + threadIdx.x;          // 96*8*8*32 = 196608
    int lane = idx & 31, mf = (idx >> 5) & 7, s = (idx >> 8) & 7, mt = idx >> 11;
    int g = lane >> 2, t = lane & 3;
    int M = mt * 128 + mf * 16 + g;
    int K = s * 16 + 2 * t;
    // reg order: (M,K)(M,K+1) | (M+8,K)(M+8,K+1) | (M,K+8)(M,K+9) | (M+8,K+8)(M+8,K+9)
    float v[8];
    v[0] = fl[(size_t)K * PP + M];           v[1] = fl[(size_t)(K + 1) * PP + M];
    v[2] = fl[(size_t)K * PP + M + 8];       v[3] = fl[(size_t)(K + 1) * PP + M + 8];
    v[4] = fl[(size_t)(K + 8) * PP + M];     v[5] = fl[(size_t)(K + 9) * PP + M];
    v[6] = fl[(size_t)(K + 8) * PP + M + 8]; v[7] = fl[(size_t)(K + 9) * PP + M + 8];
    unsigned short hh[8], ll[8];
    #pragma unroll
    for (int k = 0; k < 8; ++k) split2(v[k], hh[k], ll[k]);
    size_t base = ((size_t)(mt * 2) * 8 + s) * 8 + mf;   // variant stride = 64 (s,mf) units
    #pragma unroll
    for (int va = 0; va < 2; ++va) {
        const unsigned short* p = (va == 0) ? hh : ll;
        uint4 o;
        o.x = ((uint32_t)p[1] << 16) | p[0];
        o.y = ((uint32_t)p[3] << 16) | p[2];
        o.z = ((uint32_t)p[5] << 16) | p[4];
        o.w = ((uint32_t)p[7] << 16) | p[6];
        gA4[(base + (size_t)va * 64) * 32 + lane] = o;
    }
}

__global__ void splitB_kernel(const float* __restrict__ fr) {
    int idx = blockIdx.x * 256 + threadIdx.x;          // 48*8*4*4*32 = 196608
    int lane = idx & 31, r4 = (idx >> 5) & 3, wn = (idx >> 7) & 3;
    int s = (idx >> 9) & 7, qt = idx >> 12;
    int g = lane >> 2, t = lane & 3;
    int k0 = s * 16 + 2 * t;
    uint32_t regs[2][4];                                // [variant][j0b0,j0b1,j1b0,j1b1]
    #pragma unroll
    for (int h2 = 0; h2 < 2; ++h2) {
        int j = 2 * r4 + h2;
        int n = qt * 256 + wn * 64 + j * 8 + g;
        float v0 = fr[(size_t)k0 * QQ + n];
        float v1 = fr[(size_t)(k0 + 1) * QQ + n];
        float v8 = fr[(size_t)(k0 + 8) * QQ + n];
        float v9 = fr[(size_t)(k0 + 9) * QQ + n];
        unsigned short h0[2], h1[2], h8[2], h9[2];
        split2(v0, h0[0], h0[1]);
        split2(v1, h1[0], h1[1]);
        split2(v8, h8[0], h8[1]);
        split2(v9, h9[0], h9[1]);
        #pragma unroll
        for (int vv = 0; vv < 2; ++vv) {
            regs[vv][2 * h2]     = ((uint32_t)h1[vv] << 16) | h0[vv];   // b0: (k0,n)(k0+1,n)
            regs[vv][2 * h2 + 1] = ((uint32_t)h9[vv] << 16) | h8[vv];   // b1: (k0+8..9,n)
        }
    }
    #pragma unroll
    for (int vv = 0; vv < 2; ++vv) {
        // lane-contiguous: [qt][vv][s][wn][r4][lane]
        size_t o = ((((size_t)(qt * 2 + vv) * 8 + s) * 4 + wn) * 4 + r4) * 32 + lane;
        gB4[o] = make_uint4(regs[vv][0], regs[vv][1], regs[vv][2], regs[vv][3]);
    }
}

__global__ void init_best_kernel() {
    int p = blockIdx.x * blockDim.x + threadIdx.x;
    if (p < PP) g_best[p] = 0ull;
}

// ---------------- main GEMM + fused argmax ----------------
__global__ void __launch_bounds__(256, 1)
corr_mma_kernel() {
    extern __shared__ char smem[];
    const uint32_t sb = smem_u32(smem);
    const int tid = threadIdx.x, lane = tid & 31, wid = tid >> 5;
    const int wm = wid >> 2, wn = wid & 3;           // 2 m-warps x 4 n-warps
    const int g = lane >> 2, t = lane & 3;
    const int mt = blockIdx.x, ns = blockIdx.y;
    const int tile0 = ns * TPC;

    if (tid == 0) { MBAR_INIT(sb + 0, 1); MBAR_INIT(sb + 8, 1); }

    // A images (2 variants, 64KB) -> resident SMEM, coalesced
    {
        const uint4* srcA = gA4 + (size_t)mt * 2 * 2048;
        uint4* dstA = reinterpret_cast<uint4*>(smem + SMEM_A_OFF);
        #pragma unroll
        for (int i = 0; i < 16; ++i) dstA[i * 256 + tid] = srcA[i * 256 + tid];
    }
    __syncthreads();

    // issue stage 0 copy
    if (tid == 0) {
        MBAR_EXPECT_TX(sb + 0, B_IMG_BYTES);
        const char* src = reinterpret_cast<const char*>(gB4) +
                          (size_t)(tile0 * 2 + 0) * B_IMG_BYTES;
        asm volatile(
            "cp.async.bulk.shared::cluster.global.mbarrier::complete_tx::bytes "
            "[%0], [%1], %2, [%3];"
            :: "r"(sb + SMEM_B0_OFF), "l"(src), "r"((uint32_t)B_IMG_BYTES),
               "r"(sb + 0) : "memory");
    }

    // hoisted per-warp fragment bases
    const uint4* A0 = reinterpret_cast<const uint4*>(smem + SMEM_A_OFF) + (4 * wm) * 32 + lane;
    const uint4* A1 = reinterpret_cast<const uint4*>(smem + SMEM_A_OFF + A_IMG_BYTES) +
                      (4 * wm) * 32 + lane;
    const uint4* Bw0 = reinterpret_cast<const uint4*>(smem + SMEM_B0_OFF) + (wn << 7) + lane;
    const uint4* Bw1 = reinterpret_cast<const uint4*>(smem + SMEM_B1_OFF) + (wn << 7) + lane;

    float acc[128];
    float bv[8];
    int bq[8];
    #pragma unroll
    for (int i = 0; i < 8; ++i) { bv[i] = -3.402823466e38f; bq[i] = 0; }

    uint32_t phase[2] = {0, 0};

    for (int st = 0; st < STAGES; ++st) {
        const int b = st & 1;
        const int tile = tile0 + (st >> 1);
        const int vb = st & 1;           // 0: B=hi (A passes hi,lo), 1: B=lo (A pass hi)

        // producer: issue next stage into the other buffer
        // (safe: all threads passed the previous stage's __syncthreads)
        if (tid == 0 && st + 1 < STAGES) {
            int b2 = (st + 1) & 1;
            int tile2 = tile0 + ((st + 1) >> 1);
            int vb2 = (st + 1) & 1;
            MBAR_EXPECT_TX(sb + 8 * b2, B_IMG_BYTES);
            const char* src = reinterpret_cast<const char*>(gB4) +
                              (size_t)(tile2 * 2 + vb2) * B_IMG_BYTES;
            asm volatile(
                "cp.async.bulk.shared::cluster.global.mbarrier::complete_tx::bytes "
                "[%0], [%1], %2, [%3];"
                :: "r"(sb + (b2 ? SMEM_B1_OFF : SMEM_B0_OFF)), "l"(src),
                   "r"((uint32_t)B_IMG_BYTES), "r"(sb + 8 * b2) : "memory");
        }

        if (vb == 0) {
            #pragma unroll
            for (int i = 0; i < 128; ++i) acc[i] = 0.0f;
        }

        mbar_wait(sb + 8 * b, phase[b]); phase[b] ^= 1;
        const uint4* Bw = b ? Bw1 : Bw0;

        const int nva = 2 - vb;
        #pragma unroll
        for (int s = 0; s < 8; ++s) {
            // B fragments once per k-step, conflict-free lane-contiguous LDS.128
            uint4 bfm[4];
            const uint4* bp = Bw + (s << 9);
            #pragma unroll
            for (int r = 0; r < 4; ++r) bfm[r] = bp[r * 32];

            for (int va = 0; va < nva; ++va) {
                const uint4* Av = (va == 0) ? A0 : A1;
                uint4 af[4];
                #pragma unroll
                for (int i = 0; i < 4; ++i) af[i] = Av[(s * 8 + i) * 32];

                #pragma unroll
                for (int i = 0; i < 4; ++i) {
                    #pragma unroll
                    for (int r = 0; r < 4; ++r) {
                        mma16816(&acc[(i * 8 + 2 * r) * 4],
                                 af[i].x, af[i].y, af[i].z, af[i].w, bfm[r].x, bfm[r].y);
                        mma16816(&acc[(i * 8 + 2 * r + 1) * 4],
                                 af[i].x, af[i].y, af[i].z, af[i].w, bfm[r].z, bfm[r].w);
                    }
                }
            }
        }

        if (vb == 1) {
            // all 3 passes done for this tile: fold into running argmax (q ascending)
            const int q0 = tile * 256 + wn * 64;
            #pragma unroll
            for (int i = 0; i < 4; ++i)
                #pragma unroll
                for (int j = 0; j < 8; ++j) {
                    int qb = q0 + j * 8 + 2 * t;
                    #pragma unroll
                    for (int c = 0; c < 4; ++c) {
                        float v = acc[(i * 8 + j) * 4 + c];
                        int slot = i * 2 + (c >> 1);
                        int q = qb + (c & 1);
                        if (v > bv[slot]) { bv[slot] = v; bq[slot] = q; }
                    }
                }
        }
        __syncthreads();   // buffer-reuse protocol
    }

    // reduce across the 4 lanes sharing the same rows (t = 0..3)
    #pragma unroll
    for (int off = 1; off < 4; off <<= 1) {
        #pragma unroll
        for (int s2 = 0; s2 < 8; ++s2) {
            float ov = __shfl_xor_sync(0xFFFFFFFFu, bv[s2], off);
            int oq = __shfl_xor_sync(0xFFFFFFFFu, bq[s2], off);
            if (ov > bv[s2] || (ov == bv[s2] && oq < bq[s2])) { bv[s2] = ov; bq[s2] = oq; }
        }
    }
    if (t == 0) {
        #pragma unroll
        for (int s2 = 0; s2 < 8; ++s2) {
            int row = mt * 128 + (4 * wm + (s2 >> 1)) * 16 + g + (s2 & 1) * 8;
            unsigned long long pk = ((unsigned long long)fkey(bv[s2]) << 32) |
                                    (0xFFFFFFFFu - (unsigned)bq[s2]);
            atomicMax(&g_best[row], pk);
        }
    }
}

// ---------------- decode ----------------
__global__ void decode_kernel(float* __restrict__ out,
                              const int* __restrict__ sxp,
                              const int* __restrict__ syp) {
    int p = blockIdx.x * blockDim.x + threadIdx.x;
    if (p >= PP) return;
    int sx = sxp ? *sxp : 4;
    int sy = syp ? *syp : 4;

    unsigned long long pk = g_best[p];
    unsigned int key = (unsigned int)(pk >> 32);
    unsigned int idx = 0xFFFFFFFFu - (unsigned int)(pk & 0xFFFFFFFFu);
    float val = (key & 0x80000000u) ? __uint_as_float(key ^ 0x80000000u)
                                    : __uint_as_float(~key);
    int h = p / WW, w = p % WW;
    int i = (int)(idx / WRR), j = (int)(idx % WRR);

    out[2 * p + 0]  = (float)(w - j * sx);
    out[2 * p + 1]  = (float)(h - i * sy);
    out[2 * PP + p] = val;
}

// ---------------- launch ----------------
extern "C" void kernel_launch(void* const* d_in, const int* in_sizes, int n_in,
                              void* d_out, int out_size) {
    const float* fl = (const float*)d_in[0];
    const float* fr = (const float*)d_in[1];
    const int* sxp = (n_in > 2) ? (const int*)d_in[2] : nullptr;
    const int* syp = (n_in > 3) ? (const int*)d_in[3] : nullptr;
    float* out = (float*)d_out;
    (void)in_sizes; (void)out_size;

    cudaFuncSetAttribute(corr_mma_kernel,
                         cudaFuncAttributeMaxDynamicSharedMemorySize, SMEM_TOTAL);

    splitA_kernel<<<768, 256>>>(fl);
    splitB_kernel<<<768, 256>>>(fr);
    init_best_kernel<<<(PP + 255) / 256, 256>>>();
    corr_mma_kernel<<<dim3(PP / BM, NS), 256, SMEM_TOTAL>>>();
    decode_kernel<<<(PP + 255) / 256, 256>>>(out, sxp, syp);
}

// round 10
// speedup vs baseline: 2.8322x; 1.1096x over previous
#include <cuda_runtime.h>
#include <cuda_fp16.h>
#include <cstdint>

// ---------------- problem constants ----------------
#define CC   128
#define HH   96
#define WW   128
#define PP   (HH * WW)      // 12288 (M)
#define HRR  96
#define WRR  128
#define QQ   (HRR * WRR)    // 12288 (N)

// ---------------- tiling ----------------
#define BM    128           // CTA m-tile
#define BN    256           // CTA n-tile
#define NQT   (QQ / BN)     // 48 q-tiles
#define NS    3             // n-splits (grid.y) -> 288 CTAs = 2 waves @ 94.7%
#define TPC   (NQT / NS)    // 16 tiles per CTA
#define STAGES (2 * TPC)    // 2 B-variant stages per tile (hi, lo)

#define A_IMG_BYTES   32768                  // one A variant image per mt (fragment-ready)
#define B_IMG_BYTES   65536                  // one B variant image per qt (fragment-ready)
#define SMEM_A_OFF    1024
#define SMEM_B0_OFF   (SMEM_A_OFF + 2 * A_IMG_BYTES)       // 66560
#define SMEM_B1_OFF   (SMEM_B0_OFF + B_IMG_BYTES)          // 132096
#define SMEM_TOTAL    (SMEM_B1_OFF + B_IMG_BYTES)          // 197632

// ---------------- device scratch (no allocs allowed) ----------------
// A: [mt 96][variant 2][s 8][mf 8][lane 32] uint4  (fragment-ready fp16 pairs)
__device__ uint4 gA4[96 * 2 * 8 * 8 * 32];
// B: [qt 48][variant 2][s 8][wn 4][r4 4][lane 32] uint4 (fragment-ready, lane-contiguous)
__device__ uint4 gB4[48 * 2 * 8 * 4 * 4 * 32];
__device__ unsigned long long g_best[PP];

// ---------------- helpers ----------------
__device__ __forceinline__ uint32_t smem_u32(const void* p) {
    uint32_t a;
    asm("{ .reg .u64 t; cvta.to.shared.u64 t, %1; cvt.u32.u64 %0, t; }" : "=r"(a) : "l"(p));
    return a;
}
__device__ __forceinline__ unsigned int fkey(float f) {
    unsigned int b = __float_as_uint(f);
    return (b & 0x80000000u) ? ~b : (b | 0x80000000u);
}
__device__ __forceinline__ unsigned short h16(float x) {
    __half h = __float2half_rn(x);
    return *reinterpret_cast<unsigned short*>(&h);
}
__device__ __forceinline__ float h16v(unsigned short b) {
    __half h = *reinterpret_cast<__half*>(&b);
    return __half2float(h);
}
// 2-term fp16 split: a = hi + lo (+ ~2^-22 residual)
__device__ __forceinline__ void split2(float a, unsigned short& hi, unsigned short& lo) {
    hi = h16(a);
    lo = h16(a - h16v(hi));
}

// ---------------- mbarrier ----------------
#define MBAR_INIT(a, n) \
    asm volatile("mbarrier.init.shared.b64 [%0], %1;" :: "r"(a), "r"((uint32_t)(n)) : "memory")
#define MBAR_EXPECT_TX(a, n) \
    asm volatile("mbarrier.arrive.expect_tx.shared.b64 _, [%0], %1;" :: "r"(a), "r"((uint32_t)(n)) : "memory")
#define MBAR_ARRIVE(a) \
    asm volatile("mbarrier.arrive.shared.b64 _, [%0];" :: "r"(a) : "memory")

__device__ __forceinline__ void mbar_wait(uint32_t mbar, uint32_t phase) {
    asm volatile(
        "{\n\t.reg .pred P1;\n\t"
        "W_%=:\n\t"
        "mbarrier.try_wait.parity.acquire.cta.shared::cta.b64 P1, [%0], %1, 0x989680;\n\t"
        "@P1 bra.uni D_%=;\n\t"
        "bra.uni W_%=;\n\t"
        "D_%=:\n\t}"
        :: "r"(mbar), "r"(phase) : "memory");
}

// ---------------- legacy tensor-core mma (baseline PTX, sm_103-safe) ----------------
__device__ __forceinline__ void mma16816(float* d, uint32_t a0, uint32_t a1, uint32_t a2,
                                         uint32_t a3, uint32_t b0, uint32_t b1) {
    asm volatile(
        "mma.sync.aligned.m16n8k16.row.col.f32.f16.f16.f32 "
        "{%0,%1,%2,%3}, {%4,%5,%6,%7}, {%8,%9}, {%0,%1,%2,%3};"
        : "+f"(d[0]), "+f"(d[1]), "+f"(d[2]), "+f"(d[3])
        : "r"(a0), "r"(a1), "r"(a2), "r"(a3), "r"(b0), "r"(b1));
}

// ---------------- precompute: fragment-ready fp16 splits ----------------
__global__ void splitA_kernel(const float* __restrict__ fl) {
    int idx = blockIdx.x * 256 + threadIdx.x;          // 96*8*8*32 = 196608
    int lane = idx & 31, mf = (idx >> 5) & 7, s = (idx >> 8) & 7, mt = idx >> 11;
    int g = lane >> 2, t = lane & 3;
    int M = mt * 128 + mf * 16 + g;
    int K = s * 16 + 2 * t;
    // reg order: (M,K)(M,K+1) | (M+8,K)(M+8,K+1) | (M,K+8)(M,K+9) | (M+8,K+8)(M+8,K+9)
    float v[8];
    v[0] = fl[(size_t)K * PP + M];           v[1] = fl[(size_t)(K + 1) * PP + M];
    v[2] = fl[(size_t)K * PP + M + 8];       v[3] = fl[(size_t)(K + 1) * PP + M + 8];
    v[4] = fl[(size_t)(K + 8) * PP + M];     v[5] = fl[(size_t)(K + 9) * PP + M];
    v[6] = fl[(size_t)(K + 8) * PP + M + 8]; v[7] = fl[(size_t)(K + 9) * PP + M + 8];
    unsigned short hh[8], ll[8];
    #pragma unroll
    for (int k = 0; k < 8; ++k) split2(v[k], hh[k], ll[k]);
    size_t base = ((size_t)(mt * 2) * 8 + s) * 8 + mf;   // variant stride = 64 (s,mf) units
    #pragma unroll
    for (int va = 0; va < 2; ++va) {
        const unsigned short* p = (va == 0) ? hh : ll;
        uint4 o;
        o.x = ((uint32_t)p[1] << 16) | p[0];
        o.y = ((uint32_t)p[3] << 16) | p[2];
        o.z = ((uint32_t)p[5] << 16) | p[4];
        o.w = ((uint32_t)p[7] << 16) | p[6];
        gA4[(base + (size_t)va * 64) * 32 + lane] = o;
    }
}

__global__ void splitB_kernel(const float* __restrict__ fr) {
    int idx = blockIdx.x * 256 + threadIdx.x;          // 48*8*4*4*32 = 196608
    int lane = idx & 31, r4 = (idx >> 5) & 3, wn = (idx >> 7) & 3;
    int s = (idx >> 9) & 7, qt = idx >> 12;
    int g = lane >> 2, t = lane & 3;
    int k0 = s * 16 + 2 * t;
    uint32_t regs[2][4];                                // [variant][j0b0,j0b1,j1b0,j1b1]
    #pragma unroll
    for (int h2 = 0; h2 < 2; ++h2) {
        int j = 2 * r4 + h2;
        int n = qt * 256 + wn * 64 + j * 8 + g;
        float v0 = fr[(size_t)k0 * QQ + n];
        float v1 = fr[(size_t)(k0 + 1) * QQ + n];
        float v8 = fr[(size_t)(k0 + 8) * QQ + n];
        float v9 = fr[(size_t)(k0 + 9) * QQ + n];
        unsigned short h0[2], h1[2], h8[2], h9[2];
        split2(v0, h0[0], h0[1]);
        split2(v1, h1[0], h1[1]);
        split2(v8, h8[0], h8[1]);
        split2(v9, h9[0], h9[1]);
        #pragma unroll
        for (int vv = 0; vv < 2; ++vv) {
            regs[vv][2 * h2]     = ((uint32_t)h1[vv] << 16) | h0[vv];   // b0: (k0,n)(k0+1,n)
            regs[vv][2 * h2 + 1] = ((uint32_t)h9[vv] << 16) | h8[vv];   // b1: (k0+8..9,n)
        }
    }
    #pragma unroll
    for (int vv = 0; vv < 2; ++vv) {
        // lane-contiguous: [qt][vv][s][wn][r4][lane]
        size_t o = ((((size_t)(qt * 2 + vv) * 8 + s) * 4 + wn) * 4 + r4) * 32 + lane;
        gB4[o] = make_uint4(regs[vv][0], regs[vv][1], regs[vv][2], regs[vv][3]);
    }
}

__global__ void init_best_kernel() {
    int p = blockIdx.x * blockDim.x + threadIdx.x;
    if (p < PP) g_best[p] = 0ull;
}

// ---------------- fully-unrolled compute passes (compile-time specialized) ----------------
__device__ __forceinline__ void mma_block(float* acc, const uint4 af[4], const uint4 bfm[4]) {
    #pragma unroll
    for (int i = 0; i < 4; ++i) {
        #pragma unroll
        for (int r = 0; r < 4; ++r) {
            mma16816(&acc[(i * 8 + 2 * r) * 4],
                     af[i].x, af[i].y, af[i].z, af[i].w, bfm[r].x, bfm[r].y);
            mma16816(&acc[(i * 8 + 2 * r + 1) * 4],
                     af[i].x, af[i].y, af[i].z, af[i].w, bfm[r].z, bfm[r].w);
        }
    }
}

// B = hi variant: run A-hi and A-lo passes (2 passes)
__device__ __forceinline__ void compute_pass2(const uint4* A0, const uint4* A1,
                                              const uint4* Bw, float* acc) {
    #pragma unroll
    for (int s = 0; s < 8; ++s) {
        uint4 bfm[4];
        const uint4* bp = Bw + (s << 9);
        #pragma unroll
        for (int r = 0; r < 4; ++r) bfm[r] = bp[r * 32];
        uint4 af[4];
        #pragma unroll
        for (int i = 0; i < 4; ++i) af[i] = A0[(s * 8 + i) * 32];
        mma_block(acc, af, bfm);
        #pragma unroll
        for (int i = 0; i < 4; ++i) af[i] = A1[(s * 8 + i) * 32];
        mma_block(acc, af, bfm);
    }
}

// B = lo variant: A-hi pass only (1 pass)
__device__ __forceinline__ void compute_pass1(const uint4* A0, const uint4* Bw, float* acc) {
    #pragma unroll
    for (int s = 0; s < 8; ++s) {
        uint4 bfm[4];
        const uint4* bp = Bw + (s << 9);
        #pragma unroll
        for (int r = 0; r < 4; ++r) bfm[r] = bp[r * 32];
        uint4 af[4];
        #pragma unroll
        for (int i = 0; i < 4; ++i) af[i] = A0[(s * 8 + i) * 32];
        mma_block(acc, af, bfm);
    }
}

// ---------------- main GEMM + fused argmax ----------------
__global__ void __launch_bounds__(256, 1)
corr_mma_kernel() {
    extern __shared__ char smem[];
    const uint32_t sb = smem_u32(smem);
    const int tid = threadIdx.x, lane = tid & 31, wid = tid >> 5;
    const int wm = wid >> 2, wn = wid & 3;           // 2 m-warps x 4 n-warps
    const int g = lane >> 2, t = lane & 3;
    const int mt = blockIdx.x, ns = blockIdx.y;
    const int tile0 = ns * TPC;

    // barriers: full[2] (tx-based), free[2] (arrive-count 256)
    const uint32_t FULL0 = sb + 0, FULL1 = sb + 16, FREE0 = sb + 32, FREE1 = sb + 48;
    if (tid == 0) {
        MBAR_INIT(FULL0, 1);  MBAR_INIT(FULL1, 1);
        MBAR_INIT(FREE0, 256); MBAR_INIT(FREE1, 256);
    }

    // A images (2 variants, 64KB) -> resident SMEM, coalesced
    {
        const uint4* srcA = gA4 + (size_t)mt * 2 * 2048;
        uint4* dstA = reinterpret_cast<uint4*>(smem + SMEM_A_OFF);
        #pragma unroll
        for (int i = 0; i < 16; ++i) dstA[i * 256 + tid] = srcA[i * 256 + tid];
    }
    __syncthreads();   // barriers init + A visible to all

    // prologue: fill both buffers (stages 0 and 1)
    if (tid == 0) {
        #pragma unroll
        for (int st = 0; st < 2; ++st) {
            uint32_t fb = st ? FULL1 : FULL0;
            uint32_t dst = sb + (st ? SMEM_B1_OFF : SMEM_B0_OFF);
            MBAR_EXPECT_TX(fb, B_IMG_BYTES);
            const char* src = reinterpret_cast<const char*>(gB4) +
                              (size_t)(tile0 * 2 + st) * B_IMG_BYTES;
            asm volatile(
                "cp.async.bulk.shared::cluster.global.mbarrier::complete_tx::bytes "
                "[%0], [%1], %2, [%3];"
                :: "r"(dst), "l"(src), "r"((uint32_t)B_IMG_BYTES), "r"(fb) : "memory");
        }
    }

    // hoisted per-warp fragment bases
    const uint4* A0 = reinterpret_cast<const uint4*>(smem + SMEM_A_OFF) + (4 * wm) * 32 + lane;
    const uint4* A1 = reinterpret_cast<const uint4*>(smem + SMEM_A_OFF + A_IMG_BYTES) +
                      (4 * wm) * 32 + lane;
    const uint4* Bw0 = reinterpret_cast<const uint4*>(smem + SMEM_B0_OFF) + (wn << 7) + lane;
    const uint4* Bw1 = reinterpret_cast<const uint4*>(smem + SMEM_B1_OFF) + (wn << 7) + lane;

    float acc[128];
    float bv[8];
    int bq[8];
    #pragma unroll
    for (int i = 0; i < 8; ++i) { bv[i] = -3.402823466e38f; bq[i] = 0; }

    uint32_t pf0 = 0, pf1 = 0, pe0 = 0, pe1 = 0;

    for (int st = 0; st < STAGES; ++st) {
        const int b = st & 1;                 // buffer == variant (hi even, lo odd)
        const int tile = tile0 + (st >> 1);
        const uint32_t FULLB = b ? FULL1 : FULL0;
        const uint32_t FREEB = b ? FREE1 : FREE0;

        if (b == 0) {
            #pragma unroll
            for (int i = 0; i < 128; ++i) acc[i] = 0.0f;
            mbar_wait(FULLB, pf0); pf0 ^= 1;
            compute_pass2(A0, A1, Bw0, acc);
        } else {
            mbar_wait(FULLB, pf1); pf1 ^= 1;
            compute_pass1(A0, Bw1, acc);
        }

        // done reading buffer b -> release it (no CTA-wide barrier)
        MBAR_ARRIVE(FREEB);

        // producer: refill buffer b with stage st+2 once all 256 released it
        if (tid == 0 && st + 2 < STAGES) {
            if (b == 0) { mbar_wait(FREEB, pe0); pe0 ^= 1; }
            else        { mbar_wait(FREEB, pe1); pe1 ^= 1; }
            MBAR_EXPECT_TX(FULLB, B_IMG_BYTES);
            const char* src = reinterpret_cast<const char*>(gB4) +
                              (size_t)((tile0 + ((st + 2) >> 1)) * 2 + b) * B_IMG_BYTES;
            asm volatile(
                "cp.async.bulk.shared::cluster.global.mbarrier::complete_tx::bytes "
                "[%0], [%1], %2, [%3];"
                :: "r"(sb + (b ? SMEM_B1_OFF : SMEM_B0_OFF)), "l"(src),
                   "r"((uint32_t)B_IMG_BYTES), "r"(FULLB) : "memory");
        }

        if (b == 1) {
            // all 3 passes done for this tile: fold into running argmax (q ascending)
            const int q0 = tile * 256 + wn * 64;
            #pragma unroll
            for (int i = 0; i < 4; ++i)
                #pragma unroll
                for (int j = 0; j < 8; ++j) {
                    int qb = q0 + j * 8 + 2 * t;
                    #pragma unroll
                    for (int c = 0; c < 4; ++c) {
                        float v = acc[(i * 8 + j) * 4 + c];
                        int slot = i * 2 + (c >> 1);
                        int q = qb + (c & 1);
                        if (v > bv[slot]) { bv[slot] = v; bq[slot] = q; }
                    }
                }
        }
    }

    // reduce across the 4 lanes sharing the same rows (t = 0..3)
    #pragma unroll
    for (int off = 1; off < 4; off <<= 1) {
        #pragma unroll
        for (int s2 = 0; s2 < 8; ++s2) {
            float ov = __shfl_xor_sync(0xFFFFFFFFu, bv[s2], off);
            int oq = __shfl_xor_sync(0xFFFFFFFFu, bq[s2], off);
            if (ov > bv[s2] || (ov == bv[s2] && oq < bq[s2])) { bv[s2] = ov; bq[s2] = oq; }
        }
    }
    if (t == 0) {
        #pragma unroll
        for (int s2 = 0; s2 < 8; ++s2) {
            int row = mt * 128 + (4 * wm + (s2 >> 1)) * 16 + g + (s2 & 1) * 8;
            unsigned long long pk = ((unsigned long long)fkey(bv[s2]) << 32) |
                                    (0xFFFFFFFFu - (unsigned)bq[s2]);
            atomicMax(&g_best[row], pk);
        }
    }
}

// ---------------- decode ----------------
__global__ void decode_kernel(float* __restrict__ out,
                              const int* __restrict__ sxp,
                              const int* __restrict__ syp) {
    int p = blockIdx.x * blockDim.x + threadIdx.x;
    if (p >= PP) return;
    int sx = sxp ? *sxp : 4;
    int sy = syp ? *syp : 4;

    unsigned long long pk = g_best[p];
    unsigned int key = (unsigned int)(pk >> 32);
    unsigned int idx = 0xFFFFFFFFu - (unsigned int)(pk & 0xFFFFFFFFu);
    float val = (key & 0x80000000u) ? __uint_as_float(key ^ 0x80000000u)
                                    : __uint_as_float(~key);
    int h = p / WW, w = p % WW;
    int i = (int)(idx / WRR), j = (int)(idx % WRR);

    out[2 * p + 0]  = (float)(w - j * sx);
    out[2 * p + 1]  = (float)(h - i * sy);
    out[2 * PP + p] = val;
}

// ---------------- launch ----------------
extern "C" void kernel_launch(void* const* d_in, const int* in_sizes, int n_in,
                              void* d_out, int out_size) {
    const float* fl = (const float*)d_in[0];
    const float* fr = (const float*)d_in[1];
    const int* sxp = (n_in > 2) ? (const int*)d_in[2] : nullptr;
    const int* syp = (n_in > 3) ? (const int*)d_in[3] : nullptr;
    float* out = (float*)d_out;
    (void)in_sizes; (void)out_size;

    cudaFuncSetAttribute(corr_mma_kernel,
                         cudaFuncAttributeMaxDynamicSharedMemorySize, SMEM_TOTAL);

    splitA_kernel<<<768, 256>>>(fl);
    splitB_kernel<<<768, 256>>>(fr);
    init_best_kernel<<<(PP + 255) / 256, 256>>>();
    corr_mma_kernel<<<dim3(PP / BM, NS), 256, SMEM_TOTAL>>>();
    decode_kernel<<<(PP + 255) / 256, 256>>>(out, sxp, syp);
}